// round 12
// baseline (speedup 1.0000x reference)
#include <cuda_runtime.h>
#include <cuda_bf16.h>

#define ULL unsigned long long

__device__ __forceinline__ ULL add2(ULL a, ULL b) {
    ULL r; asm("add.rn.f32x2 %0, %1, %2;" : "=l"(r) : "l"(a), "l"(b)); return r;
}
__device__ __forceinline__ void unpk2(ULL v, float& lo, float& hi) {
    asm("mov.b64 {%0, %1}, %2;" : "=f"(lo), "=f"(hi) : "l"(v));
}
__device__ __forceinline__ void barw(int id) {   // worker-scoped named barrier, 256 threads
    asm volatile("bar.sync %0, 256;" :: "r"(id) : "memory");
}

// v12: codebook-resident + 3 fat workers (256 thr) + 4-state quanta.
// grid = #SMs, 1 block/SM, 768 threads = 3 workers x 256 threads (8 warps; 2/SMSP).
// Codebook (512 cells x 64 dims = 128 KB) staged once.
// Quantum = 4 states x 512 cells; 2048 quanta over 456 chains (chain = wk*nblocks+bid)
// -> 4.49 quanta/chain, worker loads {5,5,4}/{5,4,4}: ~5-11% imbalance
// (R11's 6 thin workers had {3,3,2,2,2,2} = 38%, which capped issue at 57%).
// Thread tile S=4 states x C=2 cells: each cv LDS.128 feeds 4 states; crossbar
// occupancy ~46% (calibrated law: cv-bytes only; uniform nx loads are free).
// acc = 8 ULL = 16 regs. Steady state: 2 worker-scoped named barriers/quantum.
// x staged NEGATED: inner loop = FADD2 + LOP3 + LDS only.
__global__ __launch_bounds__(768, 1) void PlaceCells_kernel(
    const float* __restrict__ x, const float* __restrict__ pc,
    float* __restrict__ out, int nblocks)
{
    extern __shared__ char smem[];
    float4* cs4 = reinterpret_cast<float4*>(smem);            // [16 dq][512 cells] = 128 KB
    float4* xsw = reinterpret_cast<float4*>(smem + 131072);   // [3 workers][4 st][16 dq] = 3 KB
    float*  wmp = reinterpret_cast<float*>(smem + 131072 + 3072);        // [3][8 warp][4 st]
    float*  wsp = reinterpret_cast<float*>(smem + 131072 + 3072 + 384);  // [3][8 warp][4 st]

    const int tid  = threadIdx.x;
    const int wk   = tid >> 8;        // worker 0..2
    const int wt   = tid & 255;       // thread-in-worker (cell thread)
    const int lane = tid & 31;
    const int ww   = wt >> 5;         // warp-in-worker 0..7

    // ---- stage full codebook once: cs4[dq*512 + cell] (conflict-free STS) ----
    if (tid < 512) {
        const float4* pc4 = reinterpret_cast<const float4*>(pc);
        #pragma unroll
        for (int i = 0; i < 16; i++)
            cs4[i * 512 + tid] = pc4[tid * 16 + i];
    }
    __syncthreads();    // only block-wide barrier in the kernel

    const float4* x4 = reinterpret_cast<const float4*>(x);
    const ulonglong2* csU = reinterpret_cast<const ulonglong2*>(cs4);
    const ulonglong2* xwU = reinterpret_cast<const ulonglong2*>(xsw) + wk * 64; // [4 st][16 dq]
    float4* myxs = xsw + wk * 64;
    const ULL ABSM = 0x7FFFFFFF7FFFFFFFULL;
    const int chain = wk * nblocks + blockIdx.x;   // 0..3*nblocks-1
    const int stride = 3 * nblocks;

    for (int q = chain; q < 2048; q += stride) {
        const int bs = q * 4;           // first state of quantum

        // ---- stage -x for this quantum: 4 states x 16 dq = 64 float4 ----
        if (wt < 64) {
            int s = wt >> 4, qq = wt & 15;
            float4 v = x4[(ULL)(bs + s) * 16 + qq];
            myxs[wt] = make_float4(-v.x, -v.y, -v.z, -v.w);
        }
        barw(wk + 1);   // xs visible to worker; also guards vs prev quantum's reads

        // ---- mainloop: S=4 states x C=2 cells per thread ----
        ULL acc[4][2];
        #pragma unroll
        for (int i = 0; i < 4; i++) { acc[i][0] = 0ULL; acc[i][1] = 0ULL; }

        #pragma unroll 4
        for (int dq = 0; dq < 16; dq++) {
            ulonglong2 nx[4];
            #pragma unroll
            for (int i = 0; i < 4; i++)
                nx[i] = xwU[i * 16 + dq];               // warp-uniform (uniform path, free)
            #pragma unroll
            for (int j = 0; j < 2; j++) {
                ulonglong2 cv = csU[dq * 512 + wt + j * 256];   // conflict-free
                #pragma unroll
                for (int i = 0; i < 4; i++) {
                    ULL d0 = add2(cv.x, nx[i].x) & ABSM;   // |c - x| on 2 dims
                    ULL d1 = add2(cv.y, nx[i].y) & ABSM;
                    acc[i][j] = add2(acc[i][j], d0);
                    acc[i][j] = add2(acc[i][j], d1);
                }
            }
        }

        // ---- logits u = -0.5 * l1^2 ----
        float u[4][2];
        #pragma unroll
        for (int i = 0; i < 4; i++)
            #pragma unroll
            for (int j = 0; j < 2; j++) {
                float lo, hi; unpk2(acc[i][j], lo, hi);
                float l1 = lo + hi;
                u[i][j] = -0.5f * l1 * l1;
            }

        // ---- per-warp partial (pm, ps) per state over this warp's 64 cells ----
        float pmv[4], ev[4][2];
        #pragma unroll
        for (int i = 0; i < 4; i++) {
            float pm = fmaxf(u[i][0], u[i][1]);
            #pragma unroll
            for (int off = 16; off > 0; off >>= 1)
                pm = fmaxf(pm, __shfl_xor_sync(0xffffffffu, pm, off));
            float e0 = __expf(u[i][0] - pm);
            float e1 = __expf(u[i][1] - pm);
            float ps = e0 + e1;
            #pragma unroll
            for (int off = 16; off > 0; off >>= 1)
                ps += __shfl_xor_sync(0xffffffffu, ps, off);
            pmv[i] = pm; ev[i][0] = e0; ev[i][1] = e1;
            if (lane == 0) {
                wmp[(wk * 8 + ww) * 4 + i] = pm;
                wsp[(wk * 8 + ww) * 4 + i] = ps;
            }
        }
        barw(wk + 1);   // partials visible within worker

        // ---- lane-parallel merge of 8 warp-partials per state ----
        const int k = lane & 7;   // which partial this lane owns
        #pragma unroll
        for (int i = 0; i < 4; i++) {
            float mk = wmp[(wk * 8 + k) * 4 + i];
            float M  = mk;
            #pragma unroll
            for (int off = 4; off > 0; off >>= 1)
                M = fmaxf(M, __shfl_xor_sync(0xffffffffu, M, off));
            float sk = wsp[(wk * 8 + k) * 4 + i] * __expf(mk - M);
            #pragma unroll
            for (int off = 4; off > 0; off >>= 1)
                sk += __shfl_xor_sync(0xffffffffu, sk, off);
            // scale for this warp's cached exps: exp(pm - M) / S
            float scale = __expf(pmv[i] - M) / sk;
            const ULL srow = (ULL)(bs + i);
            out[srow * 512 + wt]       = ev[i][0] * scale;
            out[srow * 512 + wt + 256] = ev[i][1] * scale;
        }
    }
}

extern "C" void kernel_launch(void* const* d_in, const int* in_sizes, int n_in,
                              void* d_out, int out_size) {
    const float* a = (const float*)d_in[0];
    const float* b = (const float*)d_in[1];
    // x is the larger tensor (8192*64), placeCells is 512*64
    const float* x  = (in_sizes[0] >= in_sizes[1]) ? a : b;
    const float* pc = (in_sizes[0] >= in_sizes[1]) ? b : a;

    const int dyn_smem = 131072 + 3072 + 768;  // codebook + x tiles + partials

    static int nsm = 0;
    if (!nsm) {
        cudaDeviceGetAttribute(&nsm, cudaDevAttrMultiProcessorCount, 0);
        if (nsm <= 0) nsm = 148;
        cudaFuncSetAttribute(PlaceCells_kernel,
                             cudaFuncAttributeMaxDynamicSharedMemorySize, dyn_smem);
    }
    PlaceCells_kernel<<<nsm, 768, dyn_smem>>>(x, pc, (float*)d_out, nsm);
}

// round 14
// speedup vs baseline: 1.1566x; 1.1566x over previous
#include <cuda_runtime.h>
#include <cuda_bf16.h>

#define ULL unsigned long long

__device__ __forceinline__ ULL add2(ULL a, ULL b) {
    ULL r; asm("add.rn.f32x2 %0, %1, %2;" : "=l"(r) : "l"(a), "l"(b)); return r;
}
__device__ __forceinline__ ULL fma2(ULL a, ULL b, ULL c) {   // a*b + c, packed f32x2
    ULL r; asm("fma.rn.f32x2 %0, %1, %2, %3;" : "=l"(r) : "l"(a), "l"(b), "l"(c)); return r;
}
__device__ __forceinline__ void unpk2(ULL v, float& lo, float& hi) {
    asm("mov.b64 {%0, %1}, %2;" : "=f"(lo), "=f"(hi) : "l"(v));
}
__device__ __forceinline__ void barw(int id) {   // worker-scoped named barrier, 128 threads
    asm volatile("bar.sync %0, 128;" :: "r"(id) : "memory");
}
__device__ __forceinline__ void cpasync16(void* sptr, const void* gptr) {
    unsigned sa = (unsigned)__cvta_generic_to_shared(sptr);
    asm volatile("cp.async.cg.shared.global [%0], [%1], 16;" :: "r"(sa), "l"(gptr) : "memory");
}
__device__ __forceinline__ void cp_commit() {
    asm volatile("cp.async.commit_group;" ::: "memory");
}
template <int N>
__device__ __forceinline__ void cp_wait() {
    asm volatile("cp.async.wait_group %0;" :: "n"(N) : "memory");
}

// v13: codebook-resident + 7 workers x 128 thr + cp.async x prefetch + full unroll.
// grid = #SMs, 1 block/SM, 896 threads = 7 workers (4 warps each).
// Codebook (512 cells x 64 dims = 128 KB) staged once.
// Quantum = 4 states x 512 cells; 2048 quanta over 1064 chains -> 1.93/chain:
// every block finishes in exactly 2 quantum-rounds (4% tail; R11 had 38%).
// Worker pipeline: x tile for quantum m+1 prefetched via cp.async (double-buffered)
// during quantum m's mainloop -> staging latency fully hidden.
// Thread tile S=4 x C=4; diff via FFMA2(x, -1, c) so x needs no negation pass.
// dq loop fully unrolled: LDS with immediate offsets, near-zero addressing ALU.
__global__ __launch_bounds__(896, 1) void PlaceCells_kernel(
    const float* __restrict__ x, const float* __restrict__ pc,
    float* __restrict__ out, int nblocks)
{
    extern __shared__ char smem[];
    float4* cs4 = reinterpret_cast<float4*>(smem);            // [16 dq][512 cells] = 128 KB
    float4* xsw = reinterpret_cast<float4*>(smem + 131072);   // [7 wk][2 buf][64] = 14 KB
    float*  wmp = reinterpret_cast<float*>(smem + 131072 + 14336);        // [7][4 warp][4 st]
    float*  wsp = reinterpret_cast<float*>(smem + 131072 + 14336 + 448);  // [7][4 warp][4 st]

    const int tid  = threadIdx.x;
    const int wk   = tid >> 7;        // worker 0..6
    const int wt   = tid & 127;       // thread-in-worker (cell thread)
    const int lane = tid & 31;
    const int ww   = wt >> 5;         // warp-in-worker 0..3

    // ---- stage full codebook once: cs4[dq*512 + cell] ----
    if (tid < 512) {
        const float4* pc4 = reinterpret_cast<const float4*>(pc);
        #pragma unroll
        for (int i = 0; i < 16; i++)
            cs4[i * 512 + tid] = pc4[tid * 16 + i];
    }

    const float4* x4 = reinterpret_cast<const float4*>(x);
    const ulonglong2* csU = reinterpret_cast<const ulonglong2*>(cs4);
    const ULL ABSM = 0x7FFFFFFF7FFFFFFFULL;
    const ULL NEG1 = 0xBF800000BF800000ULL;     // packed (-1.0f, -1.0f)

    const int chain = wk * nblocks + blockIdx.x;   // 0..7*nblocks-1
    const int NCH   = 7 * nblocks;
    const bool prod = (wt < 64);                   // x-staging producer threads

    __syncthreads();    // codebook visible (only block-wide barrier)

    // ---- prologue: prefetch x for first quantum into buf 0 ----
    if (chain < 2048 && prod) {
        cpasync16(&xsw[wk * 128 + wt], &x4[(ULL)chain * 64 + wt]);  // 4 rows, 1KB contiguous
        cp_commit();
    }

    for (int m = 0; ; m++) {
        const int q = chain + NCH * m;
        if (q >= 2048) break;
        const int buf = m & 1;
        const int bs  = q * 4;                     // first state of quantum

        if (prod) cp_wait<0>();
        barw(wk + 1);                              // x tile for quantum m visible

        // prefetch next quantum's x into the other buffer (overlaps mainloop)
        const int qn = chain + NCH * (m + 1);
        if (qn < 2048 && prod) {
            cpasync16(&xsw[wk * 128 + (buf ^ 1) * 64 + wt], &x4[(ULL)qn * 64 + wt]);
            cp_commit();
        }

        const ulonglong2* xwU =
            reinterpret_cast<const ulonglong2*>(xsw + wk * 128 + buf * 64); // [4 st][16 dq]

        // ---- mainloop: S=4 states x C=4 cells, fully unrolled ----
        ULL acc[4][4];
        #pragma unroll
        for (int i = 0; i < 4; i++)
            #pragma unroll
            for (int j = 0; j < 4; j++) acc[i][j] = 0ULL;

        #pragma unroll
        for (int dq = 0; dq < 16; dq++) {
            ulonglong2 nx[4];
            #pragma unroll
            for (int i = 0; i < 4; i++)
                nx[i] = xwU[i * 16 + dq];               // warp-uniform broadcast
            #pragma unroll
            for (int j = 0; j < 4; j++) {
                ulonglong2 cv = csU[dq * 512 + wt + j * 128];   // conflict-free
                #pragma unroll
                for (int i = 0; i < 4; i++) {
                    ULL d0 = fma2(nx[i].x, NEG1, cv.x);   // c - x on 2 dims
                    ULL d1 = fma2(nx[i].y, NEG1, cv.y);
                    acc[i][j] = add2(acc[i][j], d0 & ABSM);
                    acc[i][j] = add2(acc[i][j], d1 & ABSM);
                }
            }
        }

        // ---- logits u = -0.5 * l1^2 ----
        float u[4][4];
        #pragma unroll
        for (int i = 0; i < 4; i++)
            #pragma unroll
            for (int j = 0; j < 4; j++) {
                float lo, hi; unpk2(acc[i][j], lo, hi);
                float l1 = lo + hi;
                u[i][j] = -0.5f * l1 * l1;
            }

        // ---- per-warp partial (pm, ps) per state; cache exps in u ----
        float pmv[4];
        #pragma unroll
        for (int i = 0; i < 4; i++) {
            float pm = fmaxf(fmaxf(u[i][0], u[i][1]), fmaxf(u[i][2], u[i][3]));
            #pragma unroll
            for (int off = 16; off > 0; off >>= 1)
                pm = fmaxf(pm, __shfl_xor_sync(0xffffffffu, pm, off));
            float ps = 0.0f;
            #pragma unroll
            for (int j = 0; j < 4; j++) {
                float e = __expf(u[i][j] - pm);
                u[i][j] = e;                      // cache exp for output
                ps += e;
            }
            #pragma unroll
            for (int off = 16; off > 0; off >>= 1)
                ps += __shfl_xor_sync(0xffffffffu, ps, off);
            pmv[i] = pm;
            if (lane == 0) {
                wmp[(wk * 4 + ww) * 4 + i] = pm;
                wsp[(wk * 4 + ww) * 4 + i] = ps;
            }
        }
        barw(wk + 1);   // partials visible within worker

        // ---- lane-parallel merge of 4 warp-partials per state ----
        const int k = lane & 3;
        #pragma unroll
        for (int i = 0; i < 4; i++) {
            float mk = wmp[(wk * 4 + k) * 4 + i];
            float M  = mk;
            M = fmaxf(M, __shfl_xor_sync(0xffffffffu, M, 2));
            M = fmaxf(M, __shfl_xor_sync(0xffffffffu, M, 1));
            float sk = wsp[(wk * 4 + k) * 4 + i] * __expf(mk - M);
            sk += __shfl_xor_sync(0xffffffffu, sk, 2);
            sk += __shfl_xor_sync(0xffffffffu, sk, 1);
            float scale = __expf(pmv[i] - M) / sk;
            const ULL srow = (ULL)(bs + i);
            #pragma unroll
            for (int j = 0; j < 4; j++)
                out[srow * 512 + wt + j * 128] = u[i][j] * scale;
        }
    }
}

extern "C" void kernel_launch(void* const* d_in, const int* in_sizes, int n_in,
                              void* d_out, int out_size) {
    const float* a = (const float*)d_in[0];
    const float* b = (const float*)d_in[1];
    // x is the larger tensor (8192*64), placeCells is 512*64
    const float* x  = (in_sizes[0] >= in_sizes[1]) ? a : b;
    const float* pc = (in_sizes[0] >= in_sizes[1]) ? b : a;

    const int dyn_smem = 131072 + 14336 + 896;  // codebook + x double-buffers + partials

    static int nsm = 0;
    if (!nsm) {
        cudaDeviceGetAttribute(&nsm, cudaDevAttrMultiProcessorCount, 0);
        if (nsm <= 0) nsm = 148;
        cudaFuncSetAttribute(PlaceCells_kernel,
                             cudaFuncAttributeMaxDynamicSharedMemorySize, dyn_smem);
    }
    PlaceCells_kernel<<<nsm, 896, dyn_smem>>>(x, pc, (float*)d_out, nsm);
}